// round 2
// baseline (speedup 1.0000x reference)
#include <cuda_runtime.h>
#include <math.h>

#define BB   32768
#define FF   256
#define HH   128
#define OUTD 64

// ---------------- device scratch (no allocations allowed) ----------------
__device__ float g_xbn[BB * FF];     // BN(x)
__device__ float g_masked[BB * FF];  // mask * xbn
__device__ float g_compl[BB * FF];   // complement / prior
__device__ float g_Y[BB * FF];       // pre-BN GEMM output scratch (N=256 always)
__device__ float g_h[BB * HH];       // current activation
__device__ float g_sum[FF];
__device__ float g_sumsq[FF];
__device__ float g_a[FF];            // BN scale  (g * rsqrt(var+eps))
__device__ float g_c[FF];            // BN shift  (b - mean * a)

// ---------------- small helpers ----------------
__global__ void zero_stats_k() {
    int t = threadIdx.x;
    g_sum[t] = 0.f; g_sumsq[t] = 0.f;
}

// column sums / sum-of-squares over a [B,256] matrix. useY=1 -> g_Y, else ext.
__global__ void colstats_k(const float* __restrict__ ext, int useY) {
    const float* __restrict__ Y = useY ? g_Y : ext;
    int col = threadIdx.x;               // 256 threads = 256 columns
    int r0  = blockIdx.x * 128;          // 256 blocks * 128 rows = 32768
    float s = 0.f, s2 = 0.f;
#pragma unroll 8
    for (int r = 0; r < 128; r++) {
        float v = Y[(r0 + r) * 256 + col];
        s += v; s2 += v * v;
    }
    atomicAdd(&g_sum[col], s);
    atomicAdd(&g_sumsq[col], s2);
}

__global__ void finalize_k(const float* __restrict__ g, const float* __restrict__ b) {
    int t = threadIdx.x;
    float mean = g_sum[t] * (1.0f / BB);
    float var  = g_sumsq[t] * (1.0f / BB) - mean * mean;
    float a = g[t] * rsqrtf(var + 1e-5f);
    g_a[t] = a;
    g_c[t] = b[t] - mean * a;
    g_sum[t] = 0.f; g_sumsq[t] = 0.f;   // ready for next stage / next graph replay
}

// xbn = BN(x); compl = 1; out = 5*relu(xbn[:, :64])
__global__ void apply_x_k(const float* __restrict__ x, float* __restrict__ out) {
    int idx = blockIdx.x * 256 + threadIdx.x;   // B*F threads
    int col = idx & 255, row = idx >> 8;
    float v = x[idx] * g_a[col] + g_c[col];
    g_xbn[idx]   = v;
    g_compl[idx] = 1.0f;
    if (col < OUTD) out[row * OUTD + col] = 5.0f * fmaxf(v, 0.0f);
}

__global__ void zero_tail_k(float* __restrict__ out, int start, int total) {
    int i = start + blockIdx.x * 256 + threadIdx.x;
    if (i < total) out[i] = 0.0f;
}

// ---------------- SGEMM: g_Y[B,256] = A[B,K] @ W[K,256] ----------------
// 128x128 tile, BK=16, 256 threads, 8x8 microtile.
// asel: 0=g_xbn  1=g_masked  2=g_h  3=g_h+64(fc slice)  else ext
__global__ __launch_bounds__(256) void sgemm_k(
    const float* __restrict__ Aext, int asel, int lda,
    const float* __restrict__ W, int K)
{
    const float* __restrict__ A =
        (asel == 0) ? g_xbn :
        (asel == 1) ? g_masked :
        (asel == 2) ? g_h :
        (asel == 3) ? (g_h + OUTD) : Aext;

    __shared__ float As[16][132];
    __shared__ float Bs[16][132];

    int tid = threadIdx.x;
    int tx = tid & 15, ty = tid >> 4;
    int row0 = blockIdx.y * 128, col0 = blockIdx.x * 128;

    float acc[8][8] = {};

    int ar = tid >> 2, ac = (tid & 3) * 4;   // A tile: 128 rows x 16 k
    int br = tid >> 5, bc = (tid & 31) * 4;  // B tile: 16 k x 128 cols

    for (int k0 = 0; k0 < K; k0 += 16) {
        float4 a0 = *(const float4*)(A + (row0 + ar) * lda + k0 + ac);
        float4 a1 = *(const float4*)(A + (row0 + ar + 64) * lda + k0 + ac);
        float4 b0 = *(const float4*)(W + (k0 + br) * 256 + col0 + bc);
        float4 b1 = *(const float4*)(W + (k0 + br + 8) * 256 + col0 + bc);

        As[ac + 0][ar] = a0.x; As[ac + 1][ar] = a0.y;
        As[ac + 2][ar] = a0.z; As[ac + 3][ar] = a0.w;
        As[ac + 0][ar + 64] = a1.x; As[ac + 1][ar + 64] = a1.y;
        As[ac + 2][ar + 64] = a1.z; As[ac + 3][ar + 64] = a1.w;
        *(float4*)&Bs[br][bc]     = b0;
        *(float4*)&Bs[br + 8][bc] = b1;
        __syncthreads();

#pragma unroll
        for (int kk = 0; kk < 16; kk++) {
            float4 af0 = *(const float4*)&As[kk][ty * 8];
            float4 af1 = *(const float4*)&As[kk][ty * 8 + 4];
            float4 bf0 = *(const float4*)&Bs[kk][tx * 8];
            float4 bf1 = *(const float4*)&Bs[kk][tx * 8 + 4];
            float av[8] = {af0.x, af0.y, af0.z, af0.w, af1.x, af1.y, af1.z, af1.w};
            float bv[8] = {bf0.x, bf0.y, bf0.z, bf0.w, bf1.x, bf1.y, bf1.z, bf1.w};
#pragma unroll
            for (int i = 0; i < 8; i++)
#pragma unroll
                for (int j = 0; j < 8; j++)
                    acc[i][j] += av[i] * bv[j];
        }
        __syncthreads();
    }

#pragma unroll
    for (int i = 0; i < 8; i++) {
        float4 o0 = {acc[i][0], acc[i][1], acc[i][2], acc[i][3]};
        float4 o1 = {acc[i][4], acc[i][5], acc[i][6], acc[i][7]};
        int r = row0 + ty * 8 + i;
        *(float4*)(g_Y + r * 256 + col0 + tx * 8)     = o0;
        *(float4*)(g_Y + r * 256 + col0 + tx * 8 + 4) = o1;
    }
}

// ---------------- BN apply + GLU (+ residual), writes g_h ----------------
__global__ void act_glu_k(int residual) {
    int idx = blockIdx.x * 256 + threadIdx.x;  // B*H threads
    int j = idx & 127, row = idx >> 7;
    float y1 = g_Y[row * 256 + j]       * g_a[j]       + g_c[j];
    float y2 = g_Y[row * 256 + 128 + j] * g_a[128 + j] + g_c[128 + j];
    float v = y1 / (1.0f + expf(-y2));
    if (residual) v = (v + g_h[idx]) * 0.70710678118654752f;
    g_h[idx] = v;
}

// ---------------- softmax over 256 features, entropy, mask update --------
// one warp per row, 8 rows per CTA
__global__ void mask_k(int update, float* __restrict__ ent_out) {
    int lane = threadIdx.x & 31, w = threadIdx.x >> 5;
    int row  = blockIdx.x * 8 + w;
    int base = row * 256;

    float t[8], cm[8];
    float mx = -1e30f;
#pragma unroll
    for (int k = 0; k < 8; k++) {
        int col = lane + 32 * k;
        cm[k] = g_compl[base + col];
        t[k]  = (g_Y[base + col] * g_a[col] + g_c[col]) * cm[k];
        mx = fmaxf(mx, t[k]);
    }
#pragma unroll
    for (int o = 16; o; o >>= 1) mx = fmaxf(mx, __shfl_xor_sync(0xffffffffu, mx, o));

    float e[8], ss = 0.f;
#pragma unroll
    for (int k = 0; k < 8; k++) { e[k] = expf(t[k] - mx); ss += e[k]; }
#pragma unroll
    for (int o = 16; o; o >>= 1) ss += __shfl_xor_sync(0xffffffffu, ss, o);

    float inv = 1.0f / ss;
    float ent = 0.f;
#pragma unroll
    for (int k = 0; k < 8; k++) {
        float m = e[k] * inv;
        ent -= m * logf(m + 1e-5f);
        if (update) {
            int col = lane + 32 * k;
            g_compl[base + col]  = cm[k] * (1.5f - m);
            g_masked[base + col] = m * g_xbn[base + col];
        }
    }
#pragma unroll
    for (int o = 16; o; o >>= 1) ent += __shfl_xor_sync(0xffffffffu, ent, o);

    __shared__ float se[8];
    if (lane == 0) se[w] = ent;
    __syncthreads();
    if (threadIdx.x == 0) {
        float tot = 0.f;
#pragma unroll
        for (int i = 0; i < 8; i++) tot += se[i];
        // mean over B, divided by (S-1)=5, summed over the 5 steps
        atomicAdd(ent_out, tot * (1.0f / (32768.0f * 5.0f)));
    }
}

// ---------------- launcher ----------------
extern "C" void kernel_launch(void* const* d_in, const int* in_sizes, int n_in,
                              void* d_out, int out_size) {
    (void)in_sizes; (void)n_in;
    const float* x     = (const float*)d_in[0];
    const float* enc_g = (const float*)d_in[1];
    const float* enc_b = (const float*)d_in[2];
    const float* W1    = (const float*)d_in[3];
    const float* g1    = (const float*)d_in[4];
    const float* b1    = (const float*)d_in[5];
    const float* W2    = (const float*)d_in[6];
    const float* g2    = (const float*)d_in[7];
    const float* b2    = (const float*)d_in[8];
    const float* W3    = (const float*)d_in[9];
    const float* g3    = (const float*)d_in[10];
    const float* b3    = (const float*)d_in[11];
    const float* W4    = (const float*)d_in[12];
    const float* g4    = (const float*)d_in[13];
    const float* b4    = (const float*)d_in[14];
    const float* Wc    = (const float*)d_in[15];
    const float* gc    = (const float*)d_in[16];
    const float* bc    = (const float*)d_in[17];

    float* out = (float*)d_out;
    float* ent = out + (out_size - 1);

    dim3 ggrid(2, 256);            // N=256 -> 2 col-tiles, M=32768 -> 256 row-tiles

    // --- input BN + trivial output ---
    zero_stats_k<<<1, 256>>>();
    colstats_k<<<256, 256>>>(x, 0);
    finalize_k<<<1, 256>>>(enc_g, enc_b);
    apply_x_k<<<BB, 256>>>(x, out);
    {
        int start = BB * OUTD;
        int n = out_size - start;
        if (n > 0) zero_tail_k<<<(n + 255) / 256, 256>>>(out, start, out_size);
    }

    // --- steps 0..4 (step 5 is dead code: out uses x only, no mask at ni=5) ---
    for (int ni = 0; ni < 5; ni++) {
        // tfrm 1: [B,256] @ W1[256,256]
        sgemm_k<<<ggrid, 256>>>(nullptr, (ni == 0) ? 0 : 1, 256, W1, 256);
        colstats_k<<<256, 256>>>(nullptr, 1);
        finalize_k<<<1, 256>>>(g1, b1);
        act_glu_k<<<BB * HH / 256, 256>>>(0);

        // tfrm 2 (+res): [B,128] @ W2[128,256]
        sgemm_k<<<ggrid, 256>>>(nullptr, 2, 128, W2, 128);
        colstats_k<<<256, 256>>>(nullptr, 1);
        finalize_k<<<1, 256>>>(g2, b2);
        act_glu_k<<<BB * HH / 256, 256>>>(1);

        // tfrm 3 (+res): W3[ni]
        sgemm_k<<<ggrid, 256>>>(nullptr, 2, 128, W3 + ni * HH * 256, 128);
        colstats_k<<<256, 256>>>(nullptr, 1);
        finalize_k<<<1, 256>>>(g3 + ni * 256, b3 + ni * 256);
        act_glu_k<<<BB * HH / 256, 256>>>(1);

        // tfrm 4 (+res): W4[ni]
        sgemm_k<<<ggrid, 256>>>(nullptr, 2, 128, W4 + ni * HH * 256, 128);
        colstats_k<<<256, 256>>>(nullptr, 1);
        finalize_k<<<1, 256>>>(g4 + ni * 256, b4 + ni * 256);
        act_glu_k<<<BB * HH / 256, 256>>>(1);

        // coef: fc = h[:,64:128] @ Wc[ni][64,256]  (no GLU)
        sgemm_k<<<ggrid, 256>>>(nullptr, 3, 128, Wc + ni * OUTD * 256, 64);
        colstats_k<<<256, 256>>>(nullptr, 1);
        finalize_k<<<1, 256>>>(gc + ni * 256, bc + ni * 256);

        // softmax / entropy / mask+compl update (skip writes on last step)
        mask_k<<<BB / 8, 256>>>((ni < 4) ? 1 : 0, ent);
    }
}

// round 3
// speedup vs baseline: 1.0009x; 1.0009x over previous
#include <cuda_runtime.h>
#include <math.h>

#define BB   32768
#define FF   256
#define HH   128
#define OUTD 64

// ---------------- device scratch (no allocations allowed) ----------------
__device__ float g_xbn[BB * FF];     // BN(x)
__device__ float g_masked[BB * FF];  // mask * xbn
__device__ float g_compl[BB * FF];   // complement / prior
__device__ float g_Y[BB * FF];       // pre-BN GEMM output scratch (N=256 always)
__device__ float g_h[BB * HH];       // current activation
__device__ float g_sum[FF];
__device__ float g_sumsq[FF];
__device__ float g_a[FF];            // BN scale  (g * rsqrt(var+eps))
__device__ float g_c[FF];            // BN shift  (b - mean * a)

// ---------------- small helpers ----------------
__global__ void zero_stats_k() {
    int t = threadIdx.x;
    g_sum[t] = 0.f; g_sumsq[t] = 0.f;
}

// column sums / sum-of-squares over a [B,256] matrix. useY=1 -> g_Y, else ext.
__global__ void colstats_k(const float* __restrict__ ext, int useY) {
    const float* __restrict__ Y = useY ? g_Y : ext;
    int col = threadIdx.x;               // 256 threads = 256 columns
    int r0  = blockIdx.x * 128;          // 256 blocks * 128 rows = 32768
    float s = 0.f, s2 = 0.f;
#pragma unroll 8
    for (int r = 0; r < 128; r++) {
        float v = Y[(r0 + r) * 256 + col];
        s += v; s2 += v * v;
    }
    atomicAdd(&g_sum[col], s);
    atomicAdd(&g_sumsq[col], s2);
}

__global__ void finalize_k(const float* __restrict__ g, const float* __restrict__ b) {
    int t = threadIdx.x;
    float mean = g_sum[t] * (1.0f / BB);
    float var  = g_sumsq[t] * (1.0f / BB) - mean * mean;
    float a = g[t] * rsqrtf(var + 1e-5f);
    g_a[t] = a;
    g_c[t] = b[t] - mean * a;
    g_sum[t] = 0.f; g_sumsq[t] = 0.f;   // ready for next stage / next graph replay
}

// xbn = BN(x); compl = 1; out = 5*relu(xbn[:, :64])
__global__ void apply_x_k(const float* __restrict__ x, float* __restrict__ out) {
    int idx = blockIdx.x * 256 + threadIdx.x;   // B*F threads
    int col = idx & 255, row = idx >> 8;
    float v = x[idx] * g_a[col] + g_c[col];
    g_xbn[idx]   = v;
    g_compl[idx] = 1.0f;
    if (col < OUTD) out[row * OUTD + col] = 5.0f * fmaxf(v, 0.0f);
}

__global__ void zero_tail_k(float* __restrict__ out, int start, int total) {
    int i = start + blockIdx.x * 256 + threadIdx.x;
    if (i < total) out[i] = 0.0f;
}

// ---------------- SGEMM: g_Y[B,256] = A[B,K] @ W[K,256] ----------------
// 128x128 tile, BK=16, 256 threads, 8x8 microtile.
// asel: 0=g_xbn  1=g_masked  2=g_h  3=g_h+64(fc slice)  else ext
__global__ __launch_bounds__(256) void sgemm_k(
    const float* __restrict__ Aext, int asel, int lda,
    const float* __restrict__ W, int K)
{
    const float* __restrict__ A =
        (asel == 0) ? g_xbn :
        (asel == 1) ? g_masked :
        (asel == 2) ? g_h :
        (asel == 3) ? (g_h + OUTD) : Aext;

    __shared__ float As[16][132];
    __shared__ float Bs[16][132];

    int tid = threadIdx.x;
    int tx = tid & 15, ty = tid >> 4;
    int row0 = blockIdx.y * 128, col0 = blockIdx.x * 128;

    float acc[8][8] = {};

    int ar = tid >> 2, ac = (tid & 3) * 4;   // A tile: 128 rows x 16 k
    int br = tid >> 5, bc = (tid & 31) * 4;  // B tile: 16 k x 128 cols

    for (int k0 = 0; k0 < K; k0 += 16) {
        float4 a0 = *(const float4*)(A + (row0 + ar) * lda + k0 + ac);
        float4 a1 = *(const float4*)(A + (row0 + ar + 64) * lda + k0 + ac);
        float4 b0 = *(const float4*)(W + (k0 + br) * 256 + col0 + bc);
        float4 b1 = *(const float4*)(W + (k0 + br + 8) * 256 + col0 + bc);

        As[ac + 0][ar] = a0.x; As[ac + 1][ar] = a0.y;
        As[ac + 2][ar] = a0.z; As[ac + 3][ar] = a0.w;
        As[ac + 0][ar + 64] = a1.x; As[ac + 1][ar + 64] = a1.y;
        As[ac + 2][ar + 64] = a1.z; As[ac + 3][ar + 64] = a1.w;
        *(float4*)&Bs[br][bc]     = b0;
        *(float4*)&Bs[br + 8][bc] = b1;
        __syncthreads();

#pragma unroll
        for (int kk = 0; kk < 16; kk++) {
            float4 af0 = *(const float4*)&As[kk][ty * 8];
            float4 af1 = *(const float4*)&As[kk][ty * 8 + 4];
            float4 bf0 = *(const float4*)&Bs[kk][tx * 8];
            float4 bf1 = *(const float4*)&Bs[kk][tx * 8 + 4];
            float av[8] = {af0.x, af0.y, af0.z, af0.w, af1.x, af1.y, af1.z, af1.w};
            float bv[8] = {bf0.x, bf0.y, bf0.z, bf0.w, bf1.x, bf1.y, bf1.z, bf1.w};
#pragma unroll
            for (int i = 0; i < 8; i++)
#pragma unroll
                for (int j = 0; j < 8; j++)
                    acc[i][j] += av[i] * bv[j];
        }
        __syncthreads();
    }

#pragma unroll
    for (int i = 0; i < 8; i++) {
        float4 o0 = {acc[i][0], acc[i][1], acc[i][2], acc[i][3]};
        float4 o1 = {acc[i][4], acc[i][5], acc[i][6], acc[i][7]};
        int r = row0 + ty * 8 + i;
        *(float4*)(g_Y + r * 256 + col0 + tx * 8)     = o0;
        *(float4*)(g_Y + r * 256 + col0 + tx * 8 + 4) = o1;
    }
}

// ---------------- BN apply + GLU (+ residual), writes g_h ----------------
__global__ void act_glu_k(int residual) {
    int idx = blockIdx.x * 256 + threadIdx.x;  // B*H threads
    int j = idx & 127, row = idx >> 7;
    float y1 = g_Y[row * 256 + j]       * g_a[j]       + g_c[j];
    float y2 = g_Y[row * 256 + 128 + j] * g_a[128 + j] + g_c[128 + j];
    float v = y1 / (1.0f + expf(-y2));
    if (residual) v = (v + g_h[idx]) * 0.70710678118654752f;
    g_h[idx] = v;
}

// ---------------- softmax over 256 features, entropy, mask update --------
// one warp per row, 8 rows per CTA
__global__ void mask_k(int update, float* __restrict__ ent_out) {
    int lane = threadIdx.x & 31, w = threadIdx.x >> 5;
    int row  = blockIdx.x * 8 + w;
    int base = row * 256;

    float t[8], cm[8];
    float mx = -1e30f;
#pragma unroll
    for (int k = 0; k < 8; k++) {
        int col = lane + 32 * k;
        cm[k] = g_compl[base + col];
        t[k]  = (g_Y[base + col] * g_a[col] + g_c[col]) * cm[k];
        mx = fmaxf(mx, t[k]);
    }
#pragma unroll
    for (int o = 16; o; o >>= 1) mx = fmaxf(mx, __shfl_xor_sync(0xffffffffu, mx, o));

    float e[8], ss = 0.f;
#pragma unroll
    for (int k = 0; k < 8; k++) { e[k] = expf(t[k] - mx); ss += e[k]; }
#pragma unroll
    for (int o = 16; o; o >>= 1) ss += __shfl_xor_sync(0xffffffffu, ss, o);

    float inv = 1.0f / ss;
    float ent = 0.f;
#pragma unroll
    for (int k = 0; k < 8; k++) {
        float m = e[k] * inv;
        ent -= m * logf(m + 1e-5f);
        if (update) {
            int col = lane + 32 * k;
            g_compl[base + col]  = cm[k] * (1.5f - m);
            g_masked[base + col] = m * g_xbn[base + col];
        }
    }
#pragma unroll
    for (int o = 16; o; o >>= 1) ent += __shfl_xor_sync(0xffffffffu, ent, o);

    __shared__ float se[8];
    if (lane == 0) se[w] = ent;
    __syncthreads();
    if (threadIdx.x == 0) {
        float tot = 0.f;
#pragma unroll
        for (int i = 0; i < 8; i++) tot += se[i];
        // mean over B, divided by (S-1)=5, summed over the 5 steps
        atomicAdd(ent_out, tot * (1.0f / (32768.0f * 5.0f)));
    }
}

// ---------------- launcher ----------------
extern "C" void kernel_launch(void* const* d_in, const int* in_sizes, int n_in,
                              void* d_out, int out_size) {
    (void)in_sizes; (void)n_in;
    const float* x     = (const float*)d_in[0];
    const float* enc_g = (const float*)d_in[1];
    const float* enc_b = (const float*)d_in[2];
    const float* W1    = (const float*)d_in[3];
    const float* g1    = (const float*)d_in[4];
    const float* b1    = (const float*)d_in[5];
    const float* W2    = (const float*)d_in[6];
    const float* g2    = (const float*)d_in[7];
    const float* b2    = (const float*)d_in[8];
    const float* W3    = (const float*)d_in[9];
    const float* g3    = (const float*)d_in[10];
    const float* b3    = (const float*)d_in[11];
    const float* W4    = (const float*)d_in[12];
    const float* g4    = (const float*)d_in[13];
    const float* b4    = (const float*)d_in[14];
    const float* Wc    = (const float*)d_in[15];
    const float* gc    = (const float*)d_in[16];
    const float* bc    = (const float*)d_in[17];

    float* out = (float*)d_out;
    float* ent = out + (out_size - 1);

    dim3 ggrid(2, 256);            // N=256 -> 2 col-tiles, M=32768 -> 256 row-tiles

    // --- input BN + trivial output ---
    zero_stats_k<<<1, 256>>>();
    colstats_k<<<256, 256>>>(x, 0);
    finalize_k<<<1, 256>>>(enc_g, enc_b);
    apply_x_k<<<BB, 256>>>(x, out);
    {
        int start = BB * OUTD;
        int n = out_size - start;
        if (n > 0) zero_tail_k<<<(n + 255) / 256, 256>>>(out, start, out_size);
    }

    // --- steps 0..4 (step 5 is dead code: out uses x only, no mask at ni=5) ---
    for (int ni = 0; ni < 5; ni++) {
        // tfrm 1: [B,256] @ W1[256,256]
        sgemm_k<<<ggrid, 256>>>(nullptr, (ni == 0) ? 0 : 1, 256, W1, 256);
        colstats_k<<<256, 256>>>(nullptr, 1);
        finalize_k<<<1, 256>>>(g1, b1);
        act_glu_k<<<BB * HH / 256, 256>>>(0);

        // tfrm 2 (+res): [B,128] @ W2[128,256]
        sgemm_k<<<ggrid, 256>>>(nullptr, 2, 128, W2, 128);
        colstats_k<<<256, 256>>>(nullptr, 1);
        finalize_k<<<1, 256>>>(g2, b2);
        act_glu_k<<<BB * HH / 256, 256>>>(1);

        // tfrm 3 (+res): W3[ni]
        sgemm_k<<<ggrid, 256>>>(nullptr, 2, 128, W3 + ni * HH * 256, 128);
        colstats_k<<<256, 256>>>(nullptr, 1);
        finalize_k<<<1, 256>>>(g3 + ni * 256, b3 + ni * 256);
        act_glu_k<<<BB * HH / 256, 256>>>(1);

        // tfrm 4 (+res): W4[ni]
        sgemm_k<<<ggrid, 256>>>(nullptr, 2, 128, W4 + ni * HH * 256, 128);
        colstats_k<<<256, 256>>>(nullptr, 1);
        finalize_k<<<1, 256>>>(g4 + ni * 256, b4 + ni * 256);
        act_glu_k<<<BB * HH / 256, 256>>>(1);

        // coef: fc = h[:,64:128] @ Wc[ni][64,256]  (no GLU)
        sgemm_k<<<ggrid, 256>>>(nullptr, 3, 128, Wc + ni * OUTD * 256, 64);
        colstats_k<<<256, 256>>>(nullptr, 1);
        finalize_k<<<1, 256>>>(gc + ni * 256, bc + ni * 256);

        // softmax / entropy / mask+compl update (skip writes on last step)
        mask_k<<<BB / 8, 256>>>((ni < 4) ? 1 : 0, ent);
    }
}

// round 5
// speedup vs baseline: 1.4578x; 1.4564x over previous
#include <cuda_runtime.h>
#include <cuda_bf16.h>
#include <math.h>
#include <stdint.h>

#define BB   32768
#define FF   256
#define HH   128
#define OUTD 64
#define NSTG 26
#define BK   32
#define ASTR 40   // bf16 elements per smem row (64B data + 16B pad -> conflict-free ldmatrix)

// ---------------- device scratch ----------------
__device__ float g_xbn[BB * FF];
__device__ float g_compl[BB * FF];
__device__ float g_Y[BB * FF];
__device__ float g_h[BB * HH];
__device__ __nv_bfloat16 g_xh[BB * FF], g_xl[BB * FF];
__device__ __nv_bfloat16 g_mh[BB * FF], g_ml[BB * FF];
__device__ __nv_bfloat16 g_hh[BB * HH], g_hl[BB * HH];
__device__ __nv_bfloat16 g_Wth[507904], g_Wtl[507904];   // transposed weights [N=256, K]
__device__ float g_sum[NSTG * 256];
__device__ float g_sumsq[NSTG * 256];

// ---------------- helpers ----------------
__device__ __forceinline__ uint32_t smem_u32(const void* p) {
    return (uint32_t)__cvta_generic_to_shared(p);
}
__device__ __forceinline__ void fsplit(float v, __nv_bfloat16* h, __nv_bfloat16* l) {
    __nv_bfloat16 hb = __float2bfloat16(v);
    *h = hb;
    *l = __float2bfloat16(v - __bfloat162float(hb));
}
__device__ __forceinline__ void ldsm4(uint32_t* r, uint32_t addr) {
    asm volatile("ldmatrix.sync.aligned.m8n8.x4.shared.b16 {%0,%1,%2,%3}, [%4];"
                 : "=r"(r[0]), "=r"(r[1]), "=r"(r[2]), "=r"(r[3]) : "r"(addr));
}
__device__ __forceinline__ void mma16816(float* c, const uint32_t* a, const uint32_t* b) {
    asm volatile(
        "mma.sync.aligned.m16n8k16.row.col.f32.bf16.bf16.f32 "
        "{%0,%1,%2,%3}, {%4,%5,%6,%7}, {%8,%9}, {%0,%1,%2,%3};"
        : "+f"(c[0]), "+f"(c[1]), "+f"(c[2]), "+f"(c[3])
        : "r"(a[0]), "r"(a[1]), "r"(a[2]), "r"(a[3]), "r"(b[0]), "r"(b[1]));
}

// ---------------- stats zero ----------------
__global__ void zero_stats_k() {
    int i = blockIdx.x * 256 + threadIdx.x;
    g_sum[i] = 0.f; g_sumsq[i] = 0.f;
}

// ---------------- W transpose + split ----------------
__global__ void convw_k(const float* __restrict__ W1, const float* __restrict__ W2,
                        const float* __restrict__ W3, const float* __restrict__ W4,
                        const float* __restrict__ Wc) {
    int idx = blockIdx.x * 256 + threadIdx.x;   // < 507904
    const float* src; int base, K;
    if (idx < 65536)       { src = W1; base = 0; K = 256; }
    else if (idx < 98304)  { src = W2; base = 65536; K = 128; }
    else if (idx < 262144) { int m = (idx - 98304) >> 15; src = W3 + m * HH * FF; base = 98304 + (m << 15); K = 128; }
    else if (idx < 425984) { int m = (idx - 262144) >> 15; src = W4 + m * HH * FF; base = 262144 + (m << 15); K = 128; }
    else                   { int m = (idx - 425984) >> 14; src = Wc + m * OUTD * FF; base = 425984 + (m << 14); K = 64; }
    int local = idx - base;
    int n = local / K, k = local - n * K;       // dst layout [N=256, K]
    float v = src[k * 256 + n];
    fsplit(v, &g_Wth[idx], &g_Wtl[idx]);
}

// ---------------- column stats for x ----------------
__global__ void colstats_k(const float* __restrict__ X) {
    int col = threadIdx.x;
    int r0  = blockIdx.x * 128;
    float s = 0.f, s2 = 0.f;
#pragma unroll 8
    for (int r = 0; r < 128; r++) {
        float v = X[(r0 + r) * 256 + col];
        s += v; s2 += v * v;
    }
    atomicAdd(&g_sum[col], s);
    atomicAdd(&g_sumsq[col], s2);
}

// ---------------- input BN apply + trivial output + splits ----------------
__global__ void apply_x_k(const float* __restrict__ x, const float* __restrict__ eg,
                          const float* __restrict__ eb, float* __restrict__ out, int out_size) {
    int idx = blockIdx.x * 256 + threadIdx.x;
    int col = idx & 255, row = idx >> 8;
    float mean = g_sum[col] * (1.f / BB);
    float var  = g_sumsq[col] * (1.f / BB) - mean * mean;
    float a = eg[col] * rsqrtf(var + 1e-5f);
    float c = eb[col] - mean * a;
    float v = x[idx] * a + c;
    g_xbn[idx]   = v;
    g_compl[idx] = 1.0f;
    fsplit(v, &g_xh[idx], &g_xl[idx]);
    if (col < OUTD) out[row * OUTD + col] = 5.0f * fmaxf(v, 0.0f);
    if (idx == 0) for (int i = BB * OUTD; i < out_size; i++) out[i] = 0.0f;
}

// ---------------- split-bf16 HMMA GEMM: g_Y[B,256] = A[B,K] @ W[K,256] ---------
// acc = Ah*Bh + Ah*Bl + Al*Bh  (fp32-grade precision, drop lo*lo)
// asel: 0 = x splits  1 = masked splits  2 = h splits  3 = h splits + 64 (fc)
// Fuses column sum / sumsq into stage slice `st`.
__global__ __launch_bounds__(256, 2) void mma_k(int asel, int lda, int Woff, int K, int st) {
    __shared__ __nv_bfloat16 sAh[128 * ASTR], sAl[128 * ASTR];
    __shared__ __nv_bfloat16 sBh[128 * ASTR], sBl[128 * ASTR];

    const int tid = threadIdx.x, wid = tid >> 5, lane = tid & 31;
    const int row0 = blockIdx.y * 128, col0 = blockIdx.x * 128;

    const __nv_bfloat16 *Ah, *Al;
    if      (asel == 0) { Ah = g_xh; Al = g_xl; }
    else if (asel == 1) { Ah = g_mh; Al = g_ml; }
    else if (asel == 2) { Ah = g_hh; Al = g_hl; }
    else                { Ah = g_hh + OUTD; Al = g_hl + OUTD; }
    const __nv_bfloat16* Wh = g_Wth + Woff;
    const __nv_bfloat16* Wl = g_Wtl + Woff;

    float acc[2][8][4];
#pragma unroll
    for (int i = 0; i < 2; i++)
#pragma unroll
        for (int j = 0; j < 8; j++)
#pragma unroll
            for (int e = 0; e < 4; e++) acc[i][j][e] = 0.f;

    // per-thread load coords (2 vectors of 8 bf16 per array per iter)
    const int v0r = tid >> 2,        v0c = (tid & 3) * 8;
    const int v1r = (tid + 256) >> 2, v1c = ((tid + 256) & 3) * 8;

    // ldmatrix source addresses
    const int a_row = (wid & 3) * 32 + (lane & 15);
    const int a_koff = (lane >> 4) << 3;                 // 0 or 8
    const int b_row0 = (wid >> 2) * 64 + (lane & 7) + ((lane & 16) ? 8 : 0);
    const int b_koff = (lane & 8);                       // 0 or 8

    for (int k0 = 0; k0 < K; k0 += BK) {
        // ---- global -> smem ----
        *(uint4*)&sAh[v0r * ASTR + v0c] = *(const uint4*)(Ah + (size_t)(row0 + v0r) * lda + k0 + v0c);
        *(uint4*)&sAl[v0r * ASTR + v0c] = *(const uint4*)(Al + (size_t)(row0 + v0r) * lda + k0 + v0c);
        *(uint4*)&sAh[v1r * ASTR + v1c] = *(const uint4*)(Ah + (size_t)(row0 + v1r) * lda + k0 + v1c);
        *(uint4*)&sAl[v1r * ASTR + v1c] = *(const uint4*)(Al + (size_t)(row0 + v1r) * lda + k0 + v1c);
        *(uint4*)&sBh[v0r * ASTR + v0c] = *(const uint4*)(Wh + (size_t)(col0 + v0r) * K + k0 + v0c);
        *(uint4*)&sBl[v0r * ASTR + v0c] = *(const uint4*)(Wl + (size_t)(col0 + v0r) * K + k0 + v0c);
        *(uint4*)&sBh[v1r * ASTR + v1c] = *(const uint4*)(Wh + (size_t)(col0 + v1r) * K + k0 + v1c);
        *(uint4*)&sBl[v1r * ASTR + v1c] = *(const uint4*)(Wl + (size_t)(col0 + v1r) * K + k0 + v1c);
        __syncthreads();

#pragma unroll
        for (int kk = 0; kk < BK; kk += 16) {
            uint32_t ah[2][4], al[2][4];
#pragma unroll
            for (int mf = 0; mf < 2; mf++) {
                uint32_t aaddr = smem_u32(&sAh[(a_row + mf * 16) * ASTR + kk + a_koff]);
                ldsm4(ah[mf], aaddr);
                uint32_t aaddr2 = smem_u32(&sAl[(a_row + mf * 16) * ASTR + kk + a_koff]);
                ldsm4(al[mf], aaddr2);
            }
#pragma unroll
            for (int nf2 = 0; nf2 < 4; nf2++) {
                uint32_t bh[4], bl[4];
                uint32_t baddr = smem_u32(&sBh[(b_row0 + nf2 * 16) * ASTR + kk + b_koff]);
                ldsm4(bh, baddr);
                uint32_t baddr2 = smem_u32(&sBl[(b_row0 + nf2 * 16) * ASTR + kk + b_koff]);
                ldsm4(bl, baddr2);
#pragma unroll
                for (int mf = 0; mf < 2; mf++) {
                    mma16816(acc[mf][nf2 * 2],     ah[mf], &bh[0]);
                    mma16816(acc[mf][nf2 * 2],     ah[mf], &bl[0]);
                    mma16816(acc[mf][nf2 * 2],     al[mf], &bh[0]);
                    mma16816(acc[mf][nf2 * 2 + 1], ah[mf], &bh[2]);
                    mma16816(acc[mf][nf2 * 2 + 1], ah[mf], &bl[2]);
                    mma16816(acc[mf][nf2 * 2 + 1], al[mf], &bh[2]);
                }
            }
        }
        __syncthreads();
    }

    // ---- epilogue: write g_Y + fused column stats ----
    const int g = lane >> 2, tg = lane & 3;
    const int mbase = row0 + (wid & 3) * 32;
    const int nbase = col0 + (wid >> 2) * 64;
    float* S = g_sum   + st * 256;
    float* Q = g_sumsq + st * 256;

#pragma unroll
    for (int nf = 0; nf < 8; nf++) {
        int c = nbase + nf * 8 + tg * 2;
        float s0 = 0.f, s1 = 0.f, q0 = 0.f, q1 = 0.f;
#pragma unroll
        for (int mf = 0; mf < 2; mf++) {
            int r0 = mbase + mf * 16 + g;
            float e0 = acc[mf][nf][0], e1 = acc[mf][nf][1];
            float e2 = acc[mf][nf][2], e3 = acc[mf][nf][3];
            *(float2*)(g_Y + (size_t)r0 * 256 + c)       = make_float2(e0, e1);
            *(float2*)(g_Y + (size_t)(r0 + 8) * 256 + c) = make_float2(e2, e3);
            s0 += e0 + e2; s1 += e1 + e3;
            q0 += e0 * e0 + e2 * e2; q1 += e1 * e1 + e3 * e3;
        }
#pragma unroll
        for (int o = 4; o < 32; o <<= 1) {
            s0 += __shfl_xor_sync(0xffffffffu, s0, o);
            s1 += __shfl_xor_sync(0xffffffffu, s1, o);
            q0 += __shfl_xor_sync(0xffffffffu, q0, o);
            q1 += __shfl_xor_sync(0xffffffffu, q1, o);
        }
        int cl = c & 255;
        if (lane < 4) {
            atomicAdd(&S[cl], s0);
            atomicAdd(&S[cl + 1], s1);
            atomicAdd(&Q[cl], q0);
            atomicAdd(&Q[cl + 1], q1);
        }
    }
}

// ---------------- BN apply + GLU (+ residual), inline finalize ----------------
__global__ void act_glu_k(const float* __restrict__ g, const float* __restrict__ b,
                          int st, int residual) {
    int idx = blockIdx.x * 256 + threadIdx.x;  // B*H threads
    int j = idx & 127, row = idx >> 7;
    const float* S = g_sum   + st * 256;
    const float* Q = g_sumsq + st * 256;
    float m1 = S[j]       * (1.f / BB), m2 = S[j + 128] * (1.f / BB);
    float v1 = Q[j]       * (1.f / BB) - m1 * m1;
    float v2 = Q[j + 128] * (1.f / BB) - m2 * m2;
    float a1 = g[j]       * rsqrtf(v1 + 1e-5f);
    float a2 = g[j + 128] * rsqrtf(v2 + 1e-5f);
    float c1 = b[j]       - m1 * a1;
    float c2 = b[j + 128] - m2 * a2;
    float y1 = g_Y[row * 256 + j]       * a1 + c1;
    float y2 = g_Y[row * 256 + 128 + j] * a2 + c2;
    float v = y1 / (1.0f + expf(-y2));
    if (residual) v = (v + g_h[idx]) * 0.70710678118654752f;
    g_h[idx] = v;
    fsplit(v, &g_hh[idx], &g_hl[idx]);
}

// ---------------- softmax / entropy / mask update, inline finalize ----------
__global__ void mask_k(const float* __restrict__ gcv, const float* __restrict__ bcv,
                       int st, int update, float* __restrict__ ent_out) {
    int lane = threadIdx.x & 31, w = threadIdx.x >> 5;
    int row  = blockIdx.x * 8 + w;
    int base = row * 256;
    const float* S = g_sum   + st * 256;
    const float* Q = g_sumsq + st * 256;

    float t[8], cm[8];
    float mx = -1e30f;
#pragma unroll
    for (int k = 0; k < 8; k++) {
        int col = lane + 32 * k;
        float mean = S[col] * (1.f / BB);
        float var  = Q[col] * (1.f / BB) - mean * mean;
        float a = gcv[col] * rsqrtf(var + 1e-5f);
        float c = bcv[col] - mean * a;
        cm[k] = g_compl[base + col];
        t[k]  = (g_Y[base + col] * a + c) * cm[k];
        mx = fmaxf(mx, t[k]);
    }
#pragma unroll
    for (int o = 16; o; o >>= 1) mx = fmaxf(mx, __shfl_xor_sync(0xffffffffu, mx, o));

    float e[8], ss = 0.f;
#pragma unroll
    for (int k = 0; k < 8; k++) { e[k] = expf(t[k] - mx); ss += e[k]; }
#pragma unroll
    for (int o = 16; o; o >>= 1) ss += __shfl_xor_sync(0xffffffffu, ss, o);

    float inv = 1.0f / ss;
    float ent = 0.f;
#pragma unroll
    for (int k = 0; k < 8; k++) {
        float m = e[k] * inv;
        ent -= m * logf(m + 1e-5f);
        if (update) {
            int col = lane + 32 * k;
            g_compl[base + col] = cm[k] * (1.5f - m);
            float mv = m * g_xbn[base + col];
            fsplit(mv, &g_mh[base + col], &g_ml[base + col]);
        }
    }
#pragma unroll
    for (int o = 16; o; o >>= 1) ent += __shfl_xor_sync(0xffffffffu, ent, o);

    __shared__ float se[8];
    if (lane == 0) se[w] = ent;
    __syncthreads();
    if (threadIdx.x == 0) {
        float tot = 0.f;
#pragma unroll
        for (int i = 0; i < 8; i++) tot += se[i];
        atomicAdd(ent_out, tot * (1.0f / (32768.0f * 5.0f)));
    }
}

// ---------------- launcher ----------------
extern "C" void kernel_launch(void* const* d_in, const int* in_sizes, int n_in,
                              void* d_out, int out_size) {
    (void)in_sizes; (void)n_in;
    const float* x     = (const float*)d_in[0];
    const float* enc_g = (const float*)d_in[1];
    const float* enc_b = (const float*)d_in[2];
    const float* W1    = (const float*)d_in[3];
    const float* g1    = (const float*)d_in[4];
    const float* b1    = (const float*)d_in[5];
    const float* W2    = (const float*)d_in[6];
    const float* g2    = (const float*)d_in[7];
    const float* b2    = (const float*)d_in[8];
    const float* W3    = (const float*)d_in[9];
    const float* g3    = (const float*)d_in[10];
    const float* b3    = (const float*)d_in[11];
    const float* W4    = (const float*)d_in[12];
    const float* g4    = (const float*)d_in[13];
    const float* b4    = (const float*)d_in[14];
    const float* Wc    = (const float*)d_in[15];
    const float* gc    = (const float*)d_in[16];
    const float* bc    = (const float*)d_in[17];

    float* out = (float*)d_out;
    float* ent = out + (out_size - 1);

    dim3 ggrid(2, 256);

    // setup
    zero_stats_k<<<NSTG, 256>>>();
    convw_k<<<1984, 256>>>(W1, W2, W3, W4, Wc);
    colstats_k<<<256, 256>>>(x);
    apply_x_k<<<BB, 256>>>(x, enc_g, enc_b, out, out_size);

    // steps 0..4 (step 5 is dead code: out depends only on BN(x))
    for (int ni = 0; ni < 5; ni++) {
        int st = 1 + ni * 5;
        // G1: [B,256] @ W1
        mma_k<<<ggrid, 256>>>((ni == 0) ? 0 : 1, 256, 0, 256, st);
        act_glu_k<<<BB * HH / 256, 256>>>(g1, b1, st, 0);
        // G2 (+res)
        mma_k<<<ggrid, 256>>>(2, 128, 65536, 128, st + 1);
        act_glu_k<<<BB * HH / 256, 256>>>(g2, b2, st + 1, 1);
        // G3 (+res)
        mma_k<<<ggrid, 256>>>(2, 128, 98304 + ni * 32768, 128, st + 2);
        act_glu_k<<<BB * HH / 256, 256>>>(g3 + ni * 256, b3 + ni * 256, st + 2, 1);
        // G4 (+res)
        mma_k<<<ggrid, 256>>>(2, 128, 262144 + ni * 32768, 128, st + 3);
        act_glu_k<<<BB * HH / 256, 256>>>(g4 + ni * 256, b4 + ni * 256, st + 3, 1);
        // Gc: fc = h[:,64:128] @ Wc[ni]
        mma_k<<<ggrid, 256>>>(3, 128, 425984 + ni * 16384, 64, st + 4);
        // softmax / entropy / mask update
        mask_k<<<BB / 8, 256>>>(gc + ni * 256, bc + ni * 256, st + 4, (ni < 4) ? 1 : 0, ent);
    }
}

// round 6
// speedup vs baseline: 1.4620x; 1.0029x over previous
#include <cuda_runtime.h>
#include <cuda_bf16.h>
#include <math.h>
#include <stdint.h>

#define BB   32768
#define FF   256
#define HH   128
#define OUTD 64
#define NSTG 26
#define BK   32
#define ASTR 40   // bf16 elements per smem row (64B data + 16B pad -> conflict-free ldmatrix)

// ---------------- device scratch ----------------
__device__ float g_xbn[BB * FF];
__device__ float g_compl[BB * FF];
__device__ float g_Y[BB * FF];
__device__ float g_h[BB * HH];
__device__ __nv_bfloat16 g_xh[BB * FF], g_xl[BB * FF];
__device__ __nv_bfloat16 g_mh[BB * FF], g_ml[BB * FF];
__device__ __nv_bfloat16 g_hh[BB * HH], g_hl[BB * HH];
__device__ __nv_bfloat16 g_Wth[507904], g_Wtl[507904];   // transposed weights [N=256, K]
__device__ float g_sum[NSTG * 256];
__device__ float g_sumsq[NSTG * 256];

// ---------------- helpers ----------------
__device__ __forceinline__ uint32_t smem_u32(const void* p) {
    return (uint32_t)__cvta_generic_to_shared(p);
}
__device__ __forceinline__ void fsplit(float v, __nv_bfloat16* h, __nv_bfloat16* l) {
    __nv_bfloat16 hb = __float2bfloat16(v);
    *h = hb;
    *l = __float2bfloat16(v - __bfloat162float(hb));
}
__device__ __forceinline__ void ldsm4(uint32_t* r, uint32_t addr) {
    asm volatile("ldmatrix.sync.aligned.m8n8.x4.shared.b16 {%0,%1,%2,%3}, [%4];"
                 : "=r"(r[0]), "=r"(r[1]), "=r"(r[2]), "=r"(r[3]) : "r"(addr));
}
__device__ __forceinline__ void mma16816(float* c, const uint32_t* a, const uint32_t* b) {
    asm volatile(
        "mma.sync.aligned.m16n8k16.row.col.f32.bf16.bf16.f32 "
        "{%0,%1,%2,%3}, {%4,%5,%6,%7}, {%8,%9}, {%0,%1,%2,%3};"
        : "+f"(c[0]), "+f"(c[1]), "+f"(c[2]), "+f"(c[3])
        : "r"(a[0]), "r"(a[1]), "r"(a[2]), "r"(a[3]), "r"(b[0]), "r"(b[1]));
}

// ---------------- stats zero ----------------
__global__ void zero_stats_k() {
    int i = blockIdx.x * 256 + threadIdx.x;
    g_sum[i] = 0.f; g_sumsq[i] = 0.f;
}

// ---------------- W transpose + split ----------------
__global__ void convw_k(const float* __restrict__ W1, const float* __restrict__ W2,
                        const float* __restrict__ W3, const float* __restrict__ W4,
                        const float* __restrict__ Wc) {
    int idx = blockIdx.x * 256 + threadIdx.x;   // < 507904
    const float* src; int base, K;
    if (idx < 65536)       { src = W1; base = 0; K = 256; }
    else if (idx < 98304)  { src = W2; base = 65536; K = 128; }
    else if (idx < 262144) { int m = (idx - 98304) >> 15; src = W3 + m * HH * FF; base = 98304 + (m << 15); K = 128; }
    else if (idx < 425984) { int m = (idx - 262144) >> 15; src = W4 + m * HH * FF; base = 262144 + (m << 15); K = 128; }
    else                   { int m = (idx - 425984) >> 14; src = Wc + m * OUTD * FF; base = 425984 + (m << 14); K = 64; }
    int local = idx - base;
    int n = local / K, k = local - n * K;       // dst layout [N=256, K]
    float v = src[k * 256 + n];
    fsplit(v, &g_Wth[idx], &g_Wtl[idx]);
}

// ---------------- column stats for x ----------------
__global__ void colstats_k(const float* __restrict__ X) {
    int col = threadIdx.x;
    int r0  = blockIdx.x * 128;
    float s = 0.f, s2 = 0.f;
#pragma unroll 8
    for (int r = 0; r < 128; r++) {
        float v = X[(r0 + r) * 256 + col];
        s += v; s2 += v * v;
    }
    atomicAdd(&g_sum[col], s);
    atomicAdd(&g_sumsq[col], s2);
}

// ---------------- input BN apply + trivial output + splits ----------------
__global__ void apply_x_k(const float* __restrict__ x, const float* __restrict__ eg,
                          const float* __restrict__ eb, float* __restrict__ out, int out_size) {
    int idx = blockIdx.x * 256 + threadIdx.x;
    int col = idx & 255, row = idx >> 8;
    float mean = g_sum[col] * (1.f / BB);
    float var  = g_sumsq[col] * (1.f / BB) - mean * mean;
    float a = eg[col] * rsqrtf(var + 1e-5f);
    float c = eb[col] - mean * a;
    float v = x[idx] * a + c;
    g_xbn[idx]   = v;
    g_compl[idx] = 1.0f;
    fsplit(v, &g_xh[idx], &g_xl[idx]);
    if (col < OUTD) out[row * OUTD + col] = 5.0f * fmaxf(v, 0.0f);
    if (idx == 0) for (int i = BB * OUTD; i < out_size; i++) out[i] = 0.0f;
}

// ---------------- split-bf16 HMMA GEMM: g_Y[B,256] = A[B,K] @ W[K,256] ---------
// acc = Ah*Bh + Ah*Bl + Al*Bh  (fp32-grade precision, drop lo*lo)
// asel: 0 = x splits  1 = masked splits  2 = h splits  3 = h splits + 64 (fc)
// Fuses column sum / sumsq into stage slice `st`.
__global__ __launch_bounds__(256, 2) void mma_k(int asel, int lda, int Woff, int K, int st) {
    __shared__ __nv_bfloat16 sAh[128 * ASTR], sAl[128 * ASTR];
    __shared__ __nv_bfloat16 sBh[128 * ASTR], sBl[128 * ASTR];

    const int tid = threadIdx.x, wid = tid >> 5, lane = tid & 31;
    const int row0 = blockIdx.y * 128, col0 = blockIdx.x * 128;

    const __nv_bfloat16 *Ah, *Al;
    if      (asel == 0) { Ah = g_xh; Al = g_xl; }
    else if (asel == 1) { Ah = g_mh; Al = g_ml; }
    else if (asel == 2) { Ah = g_hh; Al = g_hl; }
    else                { Ah = g_hh + OUTD; Al = g_hl + OUTD; }
    const __nv_bfloat16* Wh = g_Wth + Woff;
    const __nv_bfloat16* Wl = g_Wtl + Woff;

    float acc[2][8][4];
#pragma unroll
    for (int i = 0; i < 2; i++)
#pragma unroll
        for (int j = 0; j < 8; j++)
#pragma unroll
            for (int e = 0; e < 4; e++) acc[i][j][e] = 0.f;

    // per-thread load coords (2 vectors of 8 bf16 per array per iter)
    const int v0r = tid >> 2,        v0c = (tid & 3) * 8;
    const int v1r = (tid + 256) >> 2, v1c = ((tid + 256) & 3) * 8;

    // ldmatrix source addresses
    const int a_row = (wid & 3) * 32 + (lane & 15);
    const int a_koff = (lane >> 4) << 3;                 // 0 or 8
    const int b_row0 = (wid >> 2) * 64 + (lane & 7) + ((lane & 16) ? 8 : 0);
    const int b_koff = (lane & 8);                       // 0 or 8

    for (int k0 = 0; k0 < K; k0 += BK) {
        // ---- global -> smem ----
        *(uint4*)&sAh[v0r * ASTR + v0c] = *(const uint4*)(Ah + (size_t)(row0 + v0r) * lda + k0 + v0c);
        *(uint4*)&sAl[v0r * ASTR + v0c] = *(const uint4*)(Al + (size_t)(row0 + v0r) * lda + k0 + v0c);
        *(uint4*)&sAh[v1r * ASTR + v1c] = *(const uint4*)(Ah + (size_t)(row0 + v1r) * lda + k0 + v1c);
        *(uint4*)&sAl[v1r * ASTR + v1c] = *(const uint4*)(Al + (size_t)(row0 + v1r) * lda + k0 + v1c);
        *(uint4*)&sBh[v0r * ASTR + v0c] = *(const uint4*)(Wh + (size_t)(col0 + v0r) * K + k0 + v0c);
        *(uint4*)&sBl[v0r * ASTR + v0c] = *(const uint4*)(Wl + (size_t)(col0 + v0r) * K + k0 + v0c);
        *(uint4*)&sBh[v1r * ASTR + v1c] = *(const uint4*)(Wh + (size_t)(col0 + v1r) * K + k0 + v1c);
        *(uint4*)&sBl[v1r * ASTR + v1c] = *(const uint4*)(Wl + (size_t)(col0 + v1r) * K + k0 + v1c);
        __syncthreads();

#pragma unroll
        for (int kk = 0; kk < BK; kk += 16) {
            uint32_t ah[2][4], al[2][4];
#pragma unroll
            for (int mf = 0; mf < 2; mf++) {
                uint32_t aaddr = smem_u32(&sAh[(a_row + mf * 16) * ASTR + kk + a_koff]);
                ldsm4(ah[mf], aaddr);
                uint32_t aaddr2 = smem_u32(&sAl[(a_row + mf * 16) * ASTR + kk + a_koff]);
                ldsm4(al[mf], aaddr2);
            }
#pragma unroll
            for (int nf2 = 0; nf2 < 4; nf2++) {
                uint32_t bh[4], bl[4];
                uint32_t baddr = smem_u32(&sBh[(b_row0 + nf2 * 16) * ASTR + kk + b_koff]);
                ldsm4(bh, baddr);
                uint32_t baddr2 = smem_u32(&sBl[(b_row0 + nf2 * 16) * ASTR + kk + b_koff]);
                ldsm4(bl, baddr2);
#pragma unroll
                for (int mf = 0; mf < 2; mf++) {
                    mma16816(acc[mf][nf2 * 2],     ah[mf], &bh[0]);
                    mma16816(acc[mf][nf2 * 2],     ah[mf], &bl[0]);
                    mma16816(acc[mf][nf2 * 2],     al[mf], &bh[0]);
                    mma16816(acc[mf][nf2 * 2 + 1], ah[mf], &bh[2]);
                    mma16816(acc[mf][nf2 * 2 + 1], ah[mf], &bl[2]);
                    mma16816(acc[mf][nf2 * 2 + 1], al[mf], &bh[2]);
                }
            }
        }
        __syncthreads();
    }

    // ---- epilogue: write g_Y + fused column stats ----
    const int g = lane >> 2, tg = lane & 3;
    const int mbase = row0 + (wid & 3) * 32;
    const int nbase = col0 + (wid >> 2) * 64;
    float* S = g_sum   + st * 256;
    float* Q = g_sumsq + st * 256;

#pragma unroll
    for (int nf = 0; nf < 8; nf++) {
        int c = nbase + nf * 8 + tg * 2;
        float s0 = 0.f, s1 = 0.f, q0 = 0.f, q1 = 0.f;
#pragma unroll
        for (int mf = 0; mf < 2; mf++) {
            int r0 = mbase + mf * 16 + g;
            float e0 = acc[mf][nf][0], e1 = acc[mf][nf][1];
            float e2 = acc[mf][nf][2], e3 = acc[mf][nf][3];
            *(float2*)(g_Y + (size_t)r0 * 256 + c)       = make_float2(e0, e1);
            *(float2*)(g_Y + (size_t)(r0 + 8) * 256 + c) = make_float2(e2, e3);
            s0 += e0 + e2; s1 += e1 + e3;
            q0 += e0 * e0 + e2 * e2; q1 += e1 * e1 + e3 * e3;
        }
#pragma unroll
        for (int o = 4; o < 32; o <<= 1) {
            s0 += __shfl_xor_sync(0xffffffffu, s0, o);
            s1 += __shfl_xor_sync(0xffffffffu, s1, o);
            q0 += __shfl_xor_sync(0xffffffffu, q0, o);
            q1 += __shfl_xor_sync(0xffffffffu, q1, o);
        }
        int cl = c & 255;
        if (lane < 4) {
            atomicAdd(&S[cl], s0);
            atomicAdd(&S[cl + 1], s1);
            atomicAdd(&Q[cl], q0);
            atomicAdd(&Q[cl + 1], q1);
        }
    }
}

// ---------------- BN apply + GLU (+ residual), inline finalize ----------------
__global__ void act_glu_k(const float* __restrict__ g, const float* __restrict__ b,
                          int st, int residual) {
    int idx = blockIdx.x * 256 + threadIdx.x;  // B*H threads
    int j = idx & 127, row = idx >> 7;
    const float* S = g_sum   + st * 256;
    const float* Q = g_sumsq + st * 256;
    float m1 = S[j]       * (1.f / BB), m2 = S[j + 128] * (1.f / BB);
    float v1 = Q[j]       * (1.f / BB) - m1 * m1;
    float v2 = Q[j + 128] * (1.f / BB) - m2 * m2;
    float a1 = g[j]       * rsqrtf(v1 + 1e-5f);
    float a2 = g[j + 128] * rsqrtf(v2 + 1e-5f);
    float c1 = b[j]       - m1 * a1;
    float c2 = b[j + 128] - m2 * a2;
    float y1 = g_Y[row * 256 + j]       * a1 + c1;
    float y2 = g_Y[row * 256 + 128 + j] * a2 + c2;
    float v = y1 / (1.0f + expf(-y2));
    if (residual) v = (v + g_h[idx]) * 0.70710678118654752f;
    g_h[idx] = v;
    fsplit(v, &g_hh[idx], &g_hl[idx]);
}

// ---------------- softmax / entropy / mask update, inline finalize ----------
__global__ void mask_k(const float* __restrict__ gcv, const float* __restrict__ bcv,
                       int st, int update, float* __restrict__ ent_out) {
    int lane = threadIdx.x & 31, w = threadIdx.x >> 5;
    int row  = blockIdx.x * 8 + w;
    int base = row * 256;
    const float* S = g_sum   + st * 256;
    const float* Q = g_sumsq + st * 256;

    float t[8], cm[8];
    float mx = -1e30f;
#pragma unroll
    for (int k = 0; k < 8; k++) {
        int col = lane + 32 * k;
        float mean = S[col] * (1.f / BB);
        float var  = Q[col] * (1.f / BB) - mean * mean;
        float a = gcv[col] * rsqrtf(var + 1e-5f);
        float c = bcv[col] - mean * a;
        cm[k] = g_compl[base + col];
        t[k]  = (g_Y[base + col] * a + c) * cm[k];
        mx = fmaxf(mx, t[k]);
    }
#pragma unroll
    for (int o = 16; o; o >>= 1) mx = fmaxf(mx, __shfl_xor_sync(0xffffffffu, mx, o));

    float e[8], ss = 0.f;
#pragma unroll
    for (int k = 0; k < 8; k++) { e[k] = expf(t[k] - mx); ss += e[k]; }
#pragma unroll
    for (int o = 16; o; o >>= 1) ss += __shfl_xor_sync(0xffffffffu, ss, o);

    float inv = 1.0f / ss;
    float ent = 0.f;
#pragma unroll
    for (int k = 0; k < 8; k++) {
        float m = e[k] * inv;
        ent -= m * logf(m + 1e-5f);
        if (update) {
            int col = lane + 32 * k;
            g_compl[base + col] = cm[k] * (1.5f - m);
            float mv = m * g_xbn[base + col];
            fsplit(mv, &g_mh[base + col], &g_ml[base + col]);
        }
    }
#pragma unroll
    for (int o = 16; o; o >>= 1) ent += __shfl_xor_sync(0xffffffffu, ent, o);

    __shared__ float se[8];
    if (lane == 0) se[w] = ent;
    __syncthreads();
    if (threadIdx.x == 0) {
        float tot = 0.f;
#pragma unroll
        for (int i = 0; i < 8; i++) tot += se[i];
        atomicAdd(ent_out, tot * (1.0f / (32768.0f * 5.0f)));
    }
}

// ---------------- launcher ----------------
extern "C" void kernel_launch(void* const* d_in, const int* in_sizes, int n_in,
                              void* d_out, int out_size) {
    (void)in_sizes; (void)n_in;
    const float* x     = (const float*)d_in[0];
    const float* enc_g = (const float*)d_in[1];
    const float* enc_b = (const float*)d_in[2];
    const float* W1    = (const float*)d_in[3];
    const float* g1    = (const float*)d_in[4];
    const float* b1    = (const float*)d_in[5];
    const float* W2    = (const float*)d_in[6];
    const float* g2    = (const float*)d_in[7];
    const float* b2    = (const float*)d_in[8];
    const float* W3    = (const float*)d_in[9];
    const float* g3    = (const float*)d_in[10];
    const float* b3    = (const float*)d_in[11];
    const float* W4    = (const float*)d_in[12];
    const float* g4    = (const float*)d_in[13];
    const float* b4    = (const float*)d_in[14];
    const float* Wc    = (const float*)d_in[15];
    const float* gc    = (const float*)d_in[16];
    const float* bc    = (const float*)d_in[17];

    float* out = (float*)d_out;
    float* ent = out + (out_size - 1);

    dim3 ggrid(2, 256);

    // setup
    zero_stats_k<<<NSTG, 256>>>();
    convw_k<<<1984, 256>>>(W1, W2, W3, W4, Wc);
    colstats_k<<<256, 256>>>(x);
    apply_x_k<<<BB, 256>>>(x, enc_g, enc_b, out, out_size);

    // steps 0..4 (step 5 is dead code: out depends only on BN(x))
    for (int ni = 0; ni < 5; ni++) {
        int st = 1 + ni * 5;
        // G1: [B,256] @ W1
        mma_k<<<ggrid, 256>>>((ni == 0) ? 0 : 1, 256, 0, 256, st);
        act_glu_k<<<BB * HH / 256, 256>>>(g1, b1, st, 0);
        // G2 (+res)
        mma_k<<<ggrid, 256>>>(2, 128, 65536, 128, st + 1);
        act_glu_k<<<BB * HH / 256, 256>>>(g2, b2, st + 1, 1);
        // G3 (+res)
        mma_k<<<ggrid, 256>>>(2, 128, 98304 + ni * 32768, 128, st + 2);
        act_glu_k<<<BB * HH / 256, 256>>>(g3 + ni * 256, b3 + ni * 256, st + 2, 1);
        // G4 (+res)
        mma_k<<<ggrid, 256>>>(2, 128, 262144 + ni * 32768, 128, st + 3);
        act_glu_k<<<BB * HH / 256, 256>>>(g4 + ni * 256, b4 + ni * 256, st + 3, 1);
        // Gc: fc = h[:,64:128] @ Wc[ni]
        mma_k<<<ggrid, 256>>>(3, 128, 425984 + ni * 16384, 64, st + 4);
        // softmax / entropy / mask update
        mask_k<<<BB / 8, 256>>>(gc + ni * 256, bc + ni * 256, st + 4, (ni < 4) ? 1 : 0, ent);
    }
}

// round 7
// speedup vs baseline: 1.8375x; 1.2568x over previous
#include <cuda_runtime.h>
#include <cuda_bf16.h>
#include <math.h>
#include <stdint.h>

#define BB   32768
#define FF   256
#define HH   128
#define OUTD 64
#define NSTG 26
#define BK   64
#define ASTR 72   // bf16 elems per smem row: 128B data + 16B pad, conflict-free ldmatrix

// ---------------- device scratch ----------------
__device__ float g_xbn[BB * FF];                  // BN(x) fp32 (for out + masked product)
__device__ float g_compl[BB * FF];
__device__ __nv_bfloat16 g_Y[BB * FF];            // GEMM output (bf16; stats taken in fp32)
__device__ float g_h[BB * HH];                    // fp32 residual chain
__device__ __nv_bfloat16 g_xb[BB * FF];           // bf16 BN(x)
__device__ __nv_bfloat16 g_mb[BB * FF];           // bf16 masked
__device__ __nv_bfloat16 g_hb[BB * HH];           // bf16 activation
__device__ __nv_bfloat16 g_Wt[507904];            // transposed weights [N=256, K]
__device__ float g_sum[NSTG * 256];
__device__ float g_sumsq[NSTG * 256];

// ---------------- helpers ----------------
__device__ __forceinline__ uint32_t smem_u32(const void* p) {
    return (uint32_t)__cvta_generic_to_shared(p);
}
__device__ __forceinline__ void ldsm4(uint32_t* r, uint32_t addr) {
    asm volatile("ldmatrix.sync.aligned.m8n8.x4.shared.b16 {%0,%1,%2,%3}, [%4];"
                 : "=r"(r[0]), "=r"(r[1]), "=r"(r[2]), "=r"(r[3]) : "r"(addr));
}
__device__ __forceinline__ void mma16816(float* c, const uint32_t* a, const uint32_t* b) {
    asm volatile(
        "mma.sync.aligned.m16n8k16.row.col.f32.bf16.bf16.f32 "
        "{%0,%1,%2,%3}, {%4,%5,%6,%7}, {%8,%9}, {%0,%1,%2,%3};"
        : "+f"(c[0]), "+f"(c[1]), "+f"(c[2]), "+f"(c[3])
        : "r"(a[0]), "r"(a[1]), "r"(a[2]), "r"(a[3]), "r"(b[0]), "r"(b[1]));
}

// ---------------- stats zero ----------------
__global__ void zero_stats_k() {
    int i = blockIdx.x * 256 + threadIdx.x;
    g_sum[i] = 0.f; g_sumsq[i] = 0.f;
}

// ---------------- W transpose -> bf16 [N=256,K] ----------------
__global__ void convw_k(const float* __restrict__ W1, const float* __restrict__ W2,
                        const float* __restrict__ W3, const float* __restrict__ W4,
                        const float* __restrict__ Wc) {
    int idx = blockIdx.x * 256 + threadIdx.x;   // < 507904
    const float* src; int base, K;
    if (idx < 65536)       { src = W1; base = 0; K = 256; }
    else if (idx < 98304)  { src = W2; base = 65536; K = 128; }
    else if (idx < 262144) { int m = (idx - 98304) >> 15; src = W3 + m * HH * FF; base = 98304 + (m << 15); K = 128; }
    else if (idx < 425984) { int m = (idx - 262144) >> 15; src = W4 + m * HH * FF; base = 262144 + (m << 15); K = 128; }
    else                   { int m = (idx - 425984) >> 14; src = Wc + m * OUTD * FF; base = 425984 + (m << 14); K = 64; }
    int local = idx - base;
    int n = local / K, k = local - n * K;
    g_Wt[idx] = __float2bfloat16(src[k * 256 + n]);
}

// ---------------- column stats for x ----------------
__global__ void colstats_k(const float* __restrict__ X) {
    int col = threadIdx.x;
    int r0  = blockIdx.x * 128;
    float s = 0.f, s2 = 0.f;
#pragma unroll 8
    for (int r = 0; r < 128; r++) {
        float v = X[(r0 + r) * 256 + col];
        s += v; s2 += v * v;
    }
    atomicAdd(&g_sum[col], s);
    atomicAdd(&g_sumsq[col], s2);
}

// ---------------- input BN apply + trivial output (x4 vectorized) ----------
__global__ void apply_x_k(const float* __restrict__ x, const float* __restrict__ eg,
                          const float* __restrict__ eb, float* __restrict__ out, int out_size) {
    int idx4 = blockIdx.x * 256 + threadIdx.x;     // BB*FF/4 threads
    int col4 = (idx4 & 63) * 4, row = idx4 >> 6;
    float4 xv = *(const float4*)(x + (size_t)idx4 * 4);
    float v[4];
#pragma unroll
    for (int i = 0; i < 4; i++) {
        int col = col4 + i;
        float mean = g_sum[col] * (1.f / BB);
        float var  = g_sumsq[col] * (1.f / BB) - mean * mean;
        float a = eg[col] * rsqrtf(var + 1e-5f);
        float c = eb[col] - mean * a;
        v[i] = ((const float*)&xv)[i] * a + c;
    }
    *(float4*)(g_xbn + (size_t)idx4 * 4)   = make_float4(v[0], v[1], v[2], v[3]);
    *(float4*)(g_compl + (size_t)idx4 * 4) = make_float4(1.f, 1.f, 1.f, 1.f);
    __nv_bfloat162 p0 = {__float2bfloat16(v[0]), __float2bfloat16(v[1])};
    __nv_bfloat162 p1 = {__float2bfloat16(v[2]), __float2bfloat16(v[3])};
    *(__nv_bfloat162*)(g_xb + (size_t)idx4 * 4)     = p0;
    *(__nv_bfloat162*)(g_xb + (size_t)idx4 * 4 + 2) = p1;
    if (col4 < OUTD) {
        float4 o = make_float4(5.f * fmaxf(v[0], 0.f), 5.f * fmaxf(v[1], 0.f),
                               5.f * fmaxf(v[2], 0.f), 5.f * fmaxf(v[3], 0.f));
        *(float4*)(out + (size_t)row * OUTD + col4) = o;
    }
    if (idx4 == 0) for (int i = BB * OUTD; i < out_size; i++) out[i] = 0.0f;
}

// ---------------- bf16 HMMA GEMM: g_Y[B,256] = A[B,K] @ W[K,256] ------------
// asel: 0 = g_xb  1 = g_mb  2 = g_hb  3 = g_hb + 64 (fc)
// Fuses column sum / sumsq (fp32) into stage slice `st`.
__global__ __launch_bounds__(256, 2) void mma_k(int asel, int lda, int Woff, int K, int st) {
    __shared__ __nv_bfloat16 sA[128 * ASTR];
    __shared__ __nv_bfloat16 sB[128 * ASTR];

    const int tid = threadIdx.x, wid = tid >> 5, lane = tid & 31;
    const int row0 = blockIdx.y * 128, col0 = blockIdx.x * 128;

    const __nv_bfloat16* A =
        (asel == 0) ? g_xb :
        (asel == 1) ? g_mb :
        (asel == 2) ? g_hb : (g_hb + OUTD);
    const __nv_bfloat16* W = g_Wt + Woff;

    float acc[2][8][4];
#pragma unroll
    for (int i = 0; i < 2; i++)
#pragma unroll
        for (int j = 0; j < 8; j++)
#pragma unroll
            for (int e = 0; e < 4; e++) acc[i][j][e] = 0.f;

    // ldmatrix source coords
    const int a_row = (wid & 3) * 32 + (lane & 15);
    const int a_koff = (lane >> 4) << 3;
    const int b_row0 = (wid >> 2) * 64 + (lane & 7) + ((lane & 16) ? 8 : 0);
    const int b_koff = (lane & 8);

    for (int k0 = 0; k0 < K; k0 += BK) {
        // ---- global -> smem: 4 vec8 per thread per matrix ----
#pragma unroll
        for (int t = 0; t < 4; t++) {
            int v = tid + t * 256;
            int r = v >> 3, c8 = (v & 7) * 8;
            *(uint4*)&sA[r * ASTR + c8] = *(const uint4*)(A + (size_t)(row0 + r) * lda + k0 + c8);
            *(uint4*)&sB[r * ASTR + c8] = *(const uint4*)(W + (size_t)(col0 + r) * K + k0 + c8);
        }
        __syncthreads();

#pragma unroll
        for (int kk = 0; kk < BK; kk += 16) {
            uint32_t ah[2][4];
#pragma unroll
            for (int mf = 0; mf < 2; mf++)
                ldsm4(ah[mf], smem_u32(&sA[(a_row + mf * 16) * ASTR + kk + a_koff]));
#pragma unroll
            for (int nf2 = 0; nf2 < 4; nf2++) {
                uint32_t bh[4];
                ldsm4(bh, smem_u32(&sB[(b_row0 + nf2 * 16) * ASTR + kk + b_koff]));
#pragma unroll
                for (int mf = 0; mf < 2; mf++) {
                    mma16816(acc[mf][nf2 * 2],     ah[mf], &bh[0]);
                    mma16816(acc[mf][nf2 * 2 + 1], ah[mf], &bh[2]);
                }
            }
        }
        __syncthreads();
    }

    // ---- epilogue: write bf16 g_Y + fused fp32 column stats ----
    const int g = lane >> 2, tg = lane & 3;
    const int mbase = row0 + (wid & 3) * 32;
    const int nbase = col0 + (wid >> 2) * 64;
    float* S = g_sum   + st * 256;
    float* Q = g_sumsq + st * 256;

#pragma unroll
    for (int nf = 0; nf < 8; nf++) {
        int c = nbase + nf * 8 + tg * 2;
        float s0 = 0.f, s1 = 0.f, q0 = 0.f, q1 = 0.f;
#pragma unroll
        for (int mf = 0; mf < 2; mf++) {
            int r0 = mbase + mf * 16 + g;
            float e0 = acc[mf][nf][0], e1 = acc[mf][nf][1];
            float e2 = acc[mf][nf][2], e3 = acc[mf][nf][3];
            __nv_bfloat162 p0 = {__float2bfloat16(e0), __float2bfloat16(e1)};
            __nv_bfloat162 p1 = {__float2bfloat16(e2), __float2bfloat16(e3)};
            *(__nv_bfloat162*)(g_Y + (size_t)r0 * 256 + c)       = p0;
            *(__nv_bfloat162*)(g_Y + (size_t)(r0 + 8) * 256 + c) = p1;
            s0 += e0 + e2; s1 += e1 + e3;
            q0 += e0 * e0 + e2 * e2; q1 += e1 * e1 + e3 * e3;
        }
#pragma unroll
        for (int o = 4; o < 32; o <<= 1) {
            s0 += __shfl_xor_sync(0xffffffffu, s0, o);
            s1 += __shfl_xor_sync(0xffffffffu, s1, o);
            q0 += __shfl_xor_sync(0xffffffffu, q0, o);
            q1 += __shfl_xor_sync(0xffffffffu, q1, o);
        }
        int cl = c & 255;
        if (lane < 4) {
            atomicAdd(&S[cl], s0);
            atomicAdd(&S[cl + 1], s1);
            atomicAdd(&Q[cl], q0);
            atomicAdd(&Q[cl + 1], q1);
        }
    }
}

// ---------------- BN apply + GLU (+ residual), x2 vectorized ----------------
__global__ void act_glu_k(const float* __restrict__ g, const float* __restrict__ b,
                          int st, int residual) {
    int idx2 = blockIdx.x * 256 + threadIdx.x;   // BB*HH/2 threads
    int j2 = (idx2 & 63) * 2, row = idx2 >> 6;
    const float* S = g_sum   + st * 256;
    const float* Q = g_sumsq + st * 256;

    __nv_bfloat162 y1p = *(const __nv_bfloat162*)(g_Y + (size_t)row * 256 + j2);
    __nv_bfloat162 y2p = *(const __nv_bfloat162*)(g_Y + (size_t)row * 256 + 128 + j2);
    float vout[2];
#pragma unroll
    for (int i = 0; i < 2; i++) {
        int j = j2 + i;
        float m1 = S[j]       * (1.f / BB), m2 = S[j + 128] * (1.f / BB);
        float v1 = Q[j]       * (1.f / BB) - m1 * m1;
        float v2 = Q[j + 128] * (1.f / BB) - m2 * m2;
        float a1 = g[j]       * rsqrtf(v1 + 1e-5f);
        float a2 = g[j + 128] * rsqrtf(v2 + 1e-5f);
        float c1 = b[j]       - m1 * a1;
        float c2 = b[j + 128] - m2 * a2;
        float y1 = __bfloat162float((i == 0) ? y1p.x : y1p.y) * a1 + c1;
        float y2 = __bfloat162float((i == 0) ? y2p.x : y2p.y) * a2 + c2;
        vout[i] = y1 / (1.0f + expf(-y2));
    }
    if (residual) {
        float2 hp = *(const float2*)(g_h + (size_t)idx2 * 2);
        vout[0] = (vout[0] + hp.x) * 0.70710678118654752f;
        vout[1] = (vout[1] + hp.y) * 0.70710678118654752f;
    }
    *(float2*)(g_h + (size_t)idx2 * 2) = make_float2(vout[0], vout[1]);
    __nv_bfloat162 hb = {__float2bfloat16(vout[0]), __float2bfloat16(vout[1])};
    *(__nv_bfloat162*)(g_hb + (size_t)idx2 * 2) = hb;
}

// ---------------- softmax / entropy / mask update ----------------
__global__ void mask_k(const float* __restrict__ gcv, const float* __restrict__ bcv,
                       int st, int update, float* __restrict__ ent_out) {
    int lane = threadIdx.x & 31, w = threadIdx.x >> 5;
    int row  = blockIdx.x * 8 + w;
    int base = row * 256;
    const float* S = g_sum   + st * 256;
    const float* Q = g_sumsq + st * 256;

    float t[8], cm[8];
    float mx = -1e30f;
#pragma unroll
    for (int k = 0; k < 8; k++) {
        int col = lane + 32 * k;
        float mean = S[col] * (1.f / BB);
        float var  = Q[col] * (1.f / BB) - mean * mean;
        float a = gcv[col] * rsqrtf(var + 1e-5f);
        float c = bcv[col] - mean * a;
        cm[k] = g_compl[base + col];
        t[k]  = (__bfloat162float(g_Y[base + col]) * a + c) * cm[k];
        mx = fmaxf(mx, t[k]);
    }
#pragma unroll
    for (int o = 16; o; o >>= 1) mx = fmaxf(mx, __shfl_xor_sync(0xffffffffu, mx, o));

    float e[8], ss = 0.f;
#pragma unroll
    for (int k = 0; k < 8; k++) { e[k] = expf(t[k] - mx); ss += e[k]; }
#pragma unroll
    for (int o = 16; o; o >>= 1) ss += __shfl_xor_sync(0xffffffffu, ss, o);

    float inv = 1.0f / ss;
    float ent = 0.f;
#pragma unroll
    for (int k = 0; k < 8; k++) {
        float m = e[k] * inv;
        ent -= m * logf(m + 1e-5f);
        if (update) {
            int col = lane + 32 * k;
            g_compl[base + col] = cm[k] * (1.5f - m);
            g_mb[base + col] = __float2bfloat16(m * g_xbn[base + col]);
        }
    }
#pragma unroll
    for (int o = 16; o; o >>= 1) ent += __shfl_xor_sync(0xffffffffu, ent, o);

    __shared__ float se[8];
    if (lane == 0) se[w] = ent;
    __syncthreads();
    if (threadIdx.x == 0) {
        float tot = 0.f;
#pragma unroll
        for (int i = 0; i < 8; i++) tot += se[i];
        atomicAdd(ent_out, tot * (1.0f / (32768.0f * 5.0f)));
    }
}

// ---------------- launcher ----------------
extern "C" void kernel_launch(void* const* d_in, const int* in_sizes, int n_in,
                              void* d_out, int out_size) {
    (void)in_sizes; (void)n_in;
    const float* x     = (const float*)d_in[0];
    const float* enc_g = (const float*)d_in[1];
    const float* enc_b = (const float*)d_in[2];
    const float* W1    = (const float*)d_in[3];
    const float* g1    = (const float*)d_in[4];
    const float* b1    = (const float*)d_in[5];
    const float* W2    = (const float*)d_in[6];
    const float* g2    = (const float*)d_in[7];
    const float* b2    = (const float*)d_in[8];
    const float* W3    = (const float*)d_in[9];
    const float* g3    = (const float*)d_in[10];
    const float* b3    = (const float*)d_in[11];
    const float* W4    = (const float*)d_in[12];
    const float* g4    = (const float*)d_in[13];
    const float* b4    = (const float*)d_in[14];
    const float* Wc    = (const float*)d_in[15];
    const float* gc    = (const float*)d_in[16];
    const float* bc    = (const float*)d_in[17];

    float* out = (float*)d_out;
    float* ent = out + (out_size - 1);

    dim3 ggrid(2, 256);

    // setup
    zero_stats_k<<<NSTG, 256>>>();
    convw_k<<<1984, 256>>>(W1, W2, W3, W4, Wc);
    colstats_k<<<256, 256>>>(x);
    apply_x_k<<<BB * FF / 1024, 256>>>(x, enc_g, enc_b, out, out_size);

    // steps 0..4 (step 5 is dead code: out depends only on BN(x))
    for (int ni = 0; ni < 5; ni++) {
        int st = 1 + ni * 5;
        // G1: [B,256] @ W1
        mma_k<<<ggrid, 256>>>((ni == 0) ? 0 : 1, 256, 0, 256, st);
        act_glu_k<<<BB * HH / 512, 256>>>(g1, b1, st, 0);
        // G2 (+res)
        mma_k<<<ggrid, 256>>>(2, 128, 65536, 128, st + 1);
        act_glu_k<<<BB * HH / 512, 256>>>(g2, b2, st + 1, 1);
        // G3 (+res)
        mma_k<<<ggrid, 256>>>(2, 128, 98304 + ni * 32768, 128, st + 2);
        act_glu_k<<<BB * HH / 512, 256>>>(g3 + ni * 256, b3 + ni * 256, st + 2, 1);
        // G4 (+res)
        mma_k<<<ggrid, 256>>>(2, 128, 262144 + ni * 32768, 128, st + 3);
        act_glu_k<<<BB * HH / 512, 256>>>(g4 + ni * 256, b4 + ni * 256, st + 3, 1);
        // Gc: fc = h[:,64:128] @ Wc[ni]
        mma_k<<<ggrid, 256>>>(3, 128, 425984 + ni * 16384, 64, st + 4);
        // softmax / entropy / mask update
        mask_k<<<BB / 8, 256>>>(gc + ni * 256, bc + ni * 256, st + 4, (ni < 4) ? 1 : 0, ent);
    }
}